// round 17
// baseline (speedup 1.0000x reference)
#include <cuda_runtime.h>
#include <cuda_bf16.h>

// MonarchAttention on GB300 — v9: v8 + x4-paired ldmatrix B loads
// (two n-tiles per ldmatrix.x4 via per-lane-group addressing) in all GEMMs.
// B=4,H=16 -> BH=64; N=4096, D=64, b=m=64, STEPS=3.

typedef unsigned int u32;

#define SCALE 0.125f
#define LDB 72   // bf16 tile row stride (144B)

#define OFF_AH 0
#define OFF_AL 9216
#define OFF_BH 18432
#define OFF_BL 27648
#define BO_VH 36864
#define BO_VL 46080
#define SMEM_B_SMALL 36864
#define SMEM_B_BIG   55296
#define SMEM_C_SMALL 37376
#define SMEM_C_BIG   55552

__device__ float g_ent[262144];                 // [bh][s][j]
__device__ __nv_bfloat16 g_qmeanH[262144], g_qmeanL[262144];
__device__ __nv_bfloat16 g_qbarH[16777216], g_qbarL[16777216];  // [bh][j][s][d]
__device__ __nv_bfloat16 g_kbarH[16777216], g_kbarL[16777216];  // [bh][s][j][d]
__device__ __nv_bfloat16 g_vbarH[16777216], g_vbarL[16777216];  // [bh][s][j][d]

// ---------------------------------------------------------------------------
__device__ __forceinline__ u32 smem_u32(const void* p) {
    u32 a;
    asm("{ .reg .u64 t; cvta.to.shared.u64 t, %1; cvt.u32.u64 %0, t; }"
        : "=r"(a) : "l"(p));
    return a;
}
__device__ __forceinline__ void cpa16(u32 s, const void* g) {
    asm volatile("cp.async.cg.shared.global [%0], [%1], 16;" :: "r"(s), "l"(g));
}
__device__ __forceinline__ void cpa_commit() {
    asm volatile("cp.async.commit_group;" ::: "memory");
}
template <int N>
__device__ __forceinline__ void cpa_waitg() {
    asm volatile("cp.async.wait_group %0;" :: "n"(N) : "memory");
}
__device__ __forceinline__ u32 pack2(float a, float b) {
    return (u32)__bfloat16_as_ushort(__float2bfloat16(a)) |
           ((u32)__bfloat16_as_ushort(__float2bfloat16(b)) << 16);
}
__device__ __forceinline__ void stPair(__nv_bfloat16* gH, __nv_bfloat16* gL,
                                       float x, float y) {
    float hx = __bfloat162float(__float2bfloat16(x));
    float hy = __bfloat162float(__float2bfloat16(y));
    *reinterpret_cast<u32*>(gH) = pack2(x, y);
    *reinterpret_cast<u32*>(gL) = pack2(x - hx, y - hy);
}

__device__ __forceinline__ void stageHL(__nv_bfloat16* Th, __nv_bfloat16* Tl,
                                        const float* src, int rs, int tid) {
#pragma unroll
    for (int it = 0; it < 8; ++it) {
        int lin = it * 128 + tid;
        int r = lin >> 4, c4 = (lin & 15) << 2;
        float4 v = *reinterpret_cast<const float4*>(src + r * rs + c4);
        float h0 = __bfloat162float(__float2bfloat16(v.x));
        float h1 = __bfloat162float(__float2bfloat16(v.y));
        float h2 = __bfloat162float(__float2bfloat16(v.z));
        float h3 = __bfloat162float(__float2bfloat16(v.w));
        *reinterpret_cast<uint2*>(Th + r * LDB + c4) =
            make_uint2(pack2(v.x, v.y), pack2(v.z, v.w));
        *reinterpret_cast<uint2*>(Tl + r * LDB + c4) =
            make_uint2(pack2(v.x - h0, v.y - h1), pack2(v.z - h2, v.w - h3));
    }
}
__device__ __forceinline__ void copyTile(u32 sbase, const __nv_bfloat16* g, int tid) {
#pragma unroll
    for (int it = 0; it < 4; ++it) {
        int idx = it * 128 + tid;
        int row = idx >> 3, ch = idx & 7;
        cpa16(sbase + row * 144 + ch * 16, g + row * 64 + ch * 8);
    }
}

// ---------------------------------------------------------------------------
__device__ __forceinline__ void mma16816(float* c, const u32* a, const u32* b) {
    asm volatile(
        "mma.sync.aligned.m16n8k16.row.col.f32.bf16.bf16.f32 "
        "{%0,%1,%2,%3}, {%4,%5,%6,%7}, {%8,%9}, {%0,%1,%2,%3};"
        : "+f"(c[0]), "+f"(c[1]), "+f"(c[2]), "+f"(c[3])
        : "r"(a[0]), "r"(a[1]), "r"(a[2]), "r"(a[3]), "r"(b[0]), "r"(b[1]));
}
__device__ __forceinline__ void ldsm4(u32 addr, u32* r) {
    asm volatile("ldmatrix.sync.aligned.m8n8.x4.shared.b16 {%0,%1,%2,%3}, [%4];"
                 : "=r"(r[0]), "=r"(r[1]), "=r"(r[2]), "=r"(r[3]) : "r"(addr));
}
__device__ __forceinline__ void ldsm4t(u32 addr, u32* r) {
    asm volatile("ldmatrix.sync.aligned.m8n8.x4.trans.shared.b16 {%0,%1,%2,%3}, [%4];"
                 : "=r"(r[0]), "=r"(r[1]), "=r"(r[2]), "=r"(r[3]) : "r"(addr));
}

// ---------------------------------------------------------------------------
__global__ void qmean_kernel(const float* __restrict__ Q) {
    int bid = blockIdx.x;
    int bh = bid >> 4;
    int s = ((bid & 15) << 2) + (threadIdx.x >> 6);
    int d = threadIdx.x & 63;
    const float* base = Q + bh * 262144 + s * 64 + d;
    float acc = 0.f;
#pragma unroll 16
    for (int i = 0; i < 64; ++i) acc += base[i * 4096];
    acc *= (1.0f / 64.0f);
    float h = __bfloat162float(__float2bfloat16(acc));
    int o = (bh << 6 | s) * 64 + d;
    g_qmeanH[o] = __float2bfloat16(acc);
    g_qmeanL[o] = __float2bfloat16(acc - h);
}

// ---------------------------------------------------------------------------
// bstep: per (bh,j): S=scale*qbar K^T; R=softmax+ent (regs); kbar=R K; (vbar=R V)
// ---------------------------------------------------------------------------
__global__ void __launch_bounds__(128)
bstep_kernel(const float* __restrict__ Kg, const float* __restrict__ Vg,
             int use_qmean, int do_vbar) {
    int bid = blockIdx.x, bh = bid >> 6, j = bid & 63;
    extern __shared__ char sm[];
    __nv_bfloat16* Ah = (__nv_bfloat16*)(sm + OFF_AH);
    __nv_bfloat16* Al = (__nv_bfloat16*)(sm + OFF_AL);
    __nv_bfloat16* Kh = (__nv_bfloat16*)(sm + OFF_BH);
    __nv_bfloat16* Kl = (__nv_bfloat16*)(sm + OFF_BL);
    __nv_bfloat16* Vh = (__nv_bfloat16*)(sm + BO_VH);
    __nv_bfloat16* Vl = (__nv_bfloat16*)(sm + BO_VL);
    int tid = threadIdx.x, w = tid >> 5, lane = tid & 31;
    int g = lane >> 2, tq = lane & 3;

    int qoff = use_qmean ? (bh << 12) : (bh * 262144 + j * 4096);
    copyTile(smem_u32(Ah), (use_qmean ? g_qmeanH : g_qbarH) + qoff, tid);
    copyTile(smem_u32(Al), (use_qmean ? g_qmeanL : g_qbarL) + qoff, tid);
    cpa_commit();
    stageHL(Kh, Kl, Kg + bh * 262144 + j * 4096, 64, tid);
    if (do_vbar) stageHL(Vh, Vl, Vg + bh * 262144 + j * 4096, 64, tid);
    cpa_waitg<0>();
    __syncthreads();

    u32 bAh = smem_u32(Ah), bAl = smem_u32(Al);
    u32 bKh = smem_u32(Kh), bKl = smem_u32(Kl);

    // lane-address components
    int arow = 16 * w + ((lane >> 3) & 1) * 8 + (lane & 7);
    int aext = (lane >> 4) * 8;
    // x4 pair, non-trans B: row = n0 + pnrow, col = k0 + pkcol
    int pnrow = (lane >> 4) * 8 + (lane & 7);
    int pkcol = ((lane >> 3) & 1) * 8;
    // x4 pair, trans B: row = k0 + pkrow, col = n0 + pncol
    int pkrow = ((lane >> 3) & 1) * 8 + (lane & 7);
    int pncol = (lane >> 4) * 8;

    // ---------------- GEMM1: S[s][t] ----------------
    float S[8][4];
#pragma unroll
    for (int nt = 0; nt < 8; ++nt)
#pragma unroll
        for (int c = 0; c < 4; ++c) S[nt][c] = 0.f;

#pragma unroll
    for (int kt = 0; kt < 4; ++kt) {
        int k0 = kt << 4;
        u32 ah[4], al[4];
        u32 aoff = (u32)((arow * LDB + k0 + aext) * 2);
        ldsm4(bAh + aoff, ah);
        ldsm4(bAl + aoff, al);
#pragma unroll
        for (int np = 0; np < 4; ++np) {
            u32 boff = (u32)(((np * 16 + pnrow) * LDB + k0 + pkcol) * 2);
            u32 b_h[4], b_l[4];
            ldsm4(bKh + boff, b_h);
            ldsm4(bKl + boff, b_l);
            mma16816(S[2 * np], ah, b_h);
            mma16816(S[2 * np], ah, b_l);
            mma16816(S[2 * np], al, b_h);
            mma16816(S[2 * np + 1], ah, b_h + 2);
            mma16816(S[2 * np + 1], ah, b_l + 2);
            mma16816(S[2 * np + 1], al, b_h + 2);
        }
    }

    // ---------------- softmax + entropy (registers) ----------------
    {
        float mx0 = -1e30f, mx1 = -1e30f;
#pragma unroll
        for (int nt = 0; nt < 8; ++nt) {
            S[nt][0] *= SCALE; S[nt][1] *= SCALE;
            S[nt][2] *= SCALE; S[nt][3] *= SCALE;
            mx0 = fmaxf(mx0, fmaxf(S[nt][0], S[nt][1]));
            mx1 = fmaxf(mx1, fmaxf(S[nt][2], S[nt][3]));
        }
        mx0 = fmaxf(mx0, __shfl_xor_sync(0xffffffffu, mx0, 1));
        mx0 = fmaxf(mx0, __shfl_xor_sync(0xffffffffu, mx0, 2));
        mx1 = fmaxf(mx1, __shfl_xor_sync(0xffffffffu, mx1, 1));
        mx1 = fmaxf(mx1, __shfl_xor_sync(0xffffffffu, mx1, 2));
        float s0 = 0.f, s1 = 0.f, e0 = 0.f, e1 = 0.f;
#pragma unroll
        for (int nt = 0; nt < 8; ++nt) {
            float g0 = S[nt][0] - mx0, g1 = S[nt][1] - mx0;
            float g2 = S[nt][2] - mx1, g3 = S[nt][3] - mx1;
            float f0 = __expf(g0), f1 = __expf(g1);
            float f2 = __expf(g2), f3 = __expf(g3);
            s0 += f0 + f1; s1 += f2 + f3;
            e0 += f0 * g0 + f1 * g1; e1 += f2 * g2 + f3 * g3;
            S[nt][0] = f0; S[nt][1] = f1; S[nt][2] = f2; S[nt][3] = f3;
        }
        s0 += __shfl_xor_sync(0xffffffffu, s0, 1);
        s0 += __shfl_xor_sync(0xffffffffu, s0, 2);
        s1 += __shfl_xor_sync(0xffffffffu, s1, 1);
        s1 += __shfl_xor_sync(0xffffffffu, s1, 2);
        e0 += __shfl_xor_sync(0xffffffffu, e0, 1);
        e0 += __shfl_xor_sync(0xffffffffu, e0, 2);
        e1 += __shfl_xor_sync(0xffffffffu, e1, 1);
        e1 += __shfl_xor_sync(0xffffffffu, e1, 2);
        float i0 = 1.0f / s0, i1 = 1.0f / s1;
        if (tq == 0) {
            g_ent[((bh << 6) + 16 * w + g) * 64 + j] = __logf(s0) - e0 * i0;
            g_ent[((bh << 6) + 16 * w + 8 + g) * 64 + j] = __logf(s1) - e1 * i1;
        }
#pragma unroll
        for (int nt = 0; nt < 8; ++nt) {
            S[nt][0] *= i0; S[nt][1] *= i0;
            S[nt][2] *= i1; S[nt][3] *= i1;
        }
    }

    // ---------------- R -> A fragments (hi/lo, registers) ----------------
    u32 Rh[4][4], Rl[4][4];
#pragma unroll
    for (int kt = 0; kt < 4; ++kt) {
        const float* e = S[2 * kt];
        const float* o = S[2 * kt + 1];
        float h;
        Rh[kt][0] = pack2(e[0], e[1]);
        Rh[kt][1] = pack2(e[2], e[3]);
        Rh[kt][2] = pack2(o[0], o[1]);
        Rh[kt][3] = pack2(o[2], o[3]);
        float r0, r1, r2, r3;
        h = __bfloat162float(__float2bfloat16(e[0])); r0 = e[0] - h;
        h = __bfloat162float(__float2bfloat16(e[1])); r1 = e[1] - h;
        h = __bfloat162float(__float2bfloat16(e[2])); r2 = e[2] - h;
        h = __bfloat162float(__float2bfloat16(e[3])); r3 = e[3] - h;
        Rl[kt][0] = pack2(r0, r1);
        Rl[kt][1] = pack2(r2, r3);
        h = __bfloat162float(__float2bfloat16(o[0])); r0 = o[0] - h;
        h = __bfloat162float(__float2bfloat16(o[1])); r1 = o[1] - h;
        h = __bfloat162float(__float2bfloat16(o[2])); r2 = o[2] - h;
        h = __bfloat162float(__float2bfloat16(o[3])); r3 = o[3] - h;
        Rl[kt][2] = pack2(r0, r1);
        Rl[kt][3] = pack2(r2, r3);
    }

    // ---------------- GEMM2: kbar = R K ----------------
    {
        float KB[8][4];
#pragma unroll
        for (int nt = 0; nt < 8; ++nt)
#pragma unroll
            for (int c = 0; c < 4; ++c) KB[nt][c] = 0.f;
#pragma unroll
        for (int kt = 0; kt < 4; ++kt) {
#pragma unroll
            for (int np = 0; np < 4; ++np) {
                u32 boff = (u32)(((kt * 16 + pkrow) * LDB + np * 16 + pncol) * 2);
                u32 b_h[4], b_l[4];
                ldsm4t(bKh + boff, b_h);
                ldsm4t(bKl + boff, b_l);
                mma16816(KB[2 * np], Rh[kt], b_h);
                mma16816(KB[2 * np], Rh[kt], b_l);
                mma16816(KB[2 * np], Rl[kt], b_h);
                mma16816(KB[2 * np + 1], Rh[kt], b_h + 2);
                mma16816(KB[2 * np + 1], Rh[kt], b_l + 2);
                mma16816(KB[2 * np + 1], Rl[kt], b_h + 2);
            }
        }
        long o0 = (long)bh * 262144 + (16 * w + g) * 4096 + j * 64;
        long o1 = o0 + 8 * 4096;
#pragma unroll
        for (int nt = 0; nt < 8; ++nt) {
            int d = nt * 8 + 2 * tq;
            stPair(g_kbarH + o0 + d, g_kbarL + o0 + d, KB[nt][0], KB[nt][1]);
            stPair(g_kbarH + o1 + d, g_kbarL + o1 + d, KB[nt][2], KB[nt][3]);
        }
    }

    // ---------------- GEMM3: vbar = R V ----------------
    if (do_vbar) {
        u32 bVh = smem_u32(Vh), bVl = smem_u32(Vl);
        float VB[8][4];
#pragma unroll
        for (int nt = 0; nt < 8; ++nt)
#pragma unroll
            for (int c = 0; c < 4; ++c) VB[nt][c] = 0.f;
#pragma unroll
        for (int kt = 0; kt < 4; ++kt) {
#pragma unroll
            for (int np = 0; np < 4; ++np) {
                u32 boff = (u32)(((kt * 16 + pkrow) * LDB + np * 16 + pncol) * 2);
                u32 b_h[4], b_l[4];
                ldsm4t(bVh + boff, b_h);
                ldsm4t(bVl + boff, b_l);
                mma16816(VB[2 * np], Rh[kt], b_h);
                mma16816(VB[2 * np], Rh[kt], b_l);
                mma16816(VB[2 * np], Rl[kt], b_h);
                mma16816(VB[2 * np + 1], Rh[kt], b_h + 2);
                mma16816(VB[2 * np + 1], Rh[kt], b_l + 2);
                mma16816(VB[2 * np + 1], Rl[kt], b_h + 2);
            }
        }
        long o0 = (long)bh * 262144 + (16 * w + g) * 4096 + j * 64;
        long o1 = o0 + 8 * 4096;
#pragma unroll
        for (int nt = 0; nt < 8; ++nt) {
            int d = nt * 8 + 2 * tq;
            stPair(g_vbarH + o0 + d, g_vbarL + o0 + d, VB[nt][0], VB[nt][1]);
            stPair(g_vbarH + o1 + d, g_vbarL + o1 + d, VB[nt][2], VB[nt][3]);
        }
    }
}

// ---------------------------------------------------------------------------
// cstep: per (bh,s): SL = scale*Q kbar^T + ent; L = softmax_j (registers)
//   non-final: L -> smem; w = col-sums; qbar = L^T Q / w  (ldsm4t A)
//   final:     out = L vbar  (register A reuse)
// ---------------------------------------------------------------------------
__global__ void __launch_bounds__(128)
cstep_kernel(const float* __restrict__ Qg, float* __restrict__ out, int is_final) {
    int bid = blockIdx.x, bh = bid >> 6, s = bid & 63;
    extern __shared__ char sm[];
    __nv_bfloat16* Qh = (__nv_bfloat16*)(sm + OFF_AH);
    __nv_bfloat16* Ql = (__nv_bfloat16*)(sm + OFF_AL);
    __nv_bfloat16* Lh = (__nv_bfloat16*)(sm + OFF_BH);   // kbar -> L
    __nv_bfloat16* Ll = (__nv_bfloat16*)(sm + OFF_BL);
    __nv_bfloat16* Vh = (__nv_bfloat16*)(sm + BO_VH);
    __nv_bfloat16* Vl = (__nv_bfloat16*)(sm + BO_VL);
    float* sEnt = (float*)(sm + (is_final ? 55296 : 36864));
    float* sW = sEnt + 64;
    int tid = threadIdx.x, w = tid >> 5, lane = tid & 31;
    int g = lane >> 2, tq = lane & 3;

    int koff = bh * 262144 + s * 4096;
    copyTile(smem_u32(Lh), g_kbarH + koff, tid);
    copyTile(smem_u32(Ll), g_kbarL + koff, tid);
    if (is_final) {
        copyTile(smem_u32(Vh), g_vbarH + koff, tid);
        copyTile(smem_u32(Vl), g_vbarL + koff, tid);
    }
    cpa_commit();
    stageHL(Qh, Ql, Qg + bh * 262144 + s * 64, 4096, tid);
    if (tid < 64) sEnt[tid] = g_ent[((bh << 6) + s) * 64 + tid];
    cpa_waitg<0>();
    __syncthreads();

    u32 bQh = smem_u32(Qh), bQl = smem_u32(Ql);
    u32 bLh = smem_u32(Lh), bLl = smem_u32(Ll);

    int arow = 16 * w + ((lane >> 3) & 1) * 8 + (lane & 7);
    int aext = (lane >> 4) * 8;
    int pnrow = (lane >> 4) * 8 + (lane & 7);
    int pkcol = ((lane >> 3) & 1) * 8;
    int pkrow = ((lane >> 3) & 1) * 8 + (lane & 7);
    int pncol = (lane >> 4) * 8;
    int atrow = (lane >> 4) * 8 + (lane & 7);
    int atcol = 16 * w + ((lane >> 3) & 1) * 8;

    // ---------------- GEMM1: SL[i][j] = Q(i,d).kbar(j,d) ----------------
    float S[8][4];
#pragma unroll
    for (int nt = 0; nt < 8; ++nt)
#pragma unroll
        for (int c = 0; c < 4; ++c) S[nt][c] = 0.f;

#pragma unroll
    for (int kt = 0; kt < 4; ++kt) {
        int k0 = kt << 4;
        u32 ah[4], al[4];
        u32 aoff = (u32)((arow * LDB + k0 + aext) * 2);
        ldsm4(bQh + aoff, ah);
        ldsm4(bQl + aoff, al);
#pragma unroll
        for (int np = 0; np < 4; ++np) {
            u32 boff = (u32)(((np * 16 + pnrow) * LDB + k0 + pkcol) * 2);
            u32 b_h[4], b_l[4];
            ldsm4(bLh + boff, b_h);
            ldsm4(bLl + boff, b_l);
            mma16816(S[2 * np], ah, b_h);
            mma16816(S[2 * np], ah, b_l);
            mma16816(S[2 * np], al, b_h);
            mma16816(S[2 * np + 1], ah, b_h + 2);
            mma16816(S[2 * np + 1], ah, b_l + 2);
            mma16816(S[2 * np + 1], al, b_h + 2);
        }
    }

    // ---------------- softmax over j (registers, + ent) ----------------
    {
        float mx0 = -1e30f, mx1 = -1e30f;
#pragma unroll
        for (int nt = 0; nt < 8; ++nt) {
            int j0 = nt * 8 + 2 * tq;
            float e0c = sEnt[j0], e1c = sEnt[j0 + 1];
            S[nt][0] = S[nt][0] * SCALE + e0c;
            S[nt][1] = S[nt][1] * SCALE + e1c;
            S[nt][2] = S[nt][2] * SCALE + e0c;
            S[nt][3] = S[nt][3] * SCALE + e1c;
            mx0 = fmaxf(mx0, fmaxf(S[nt][0], S[nt][1]));
            mx1 = fmaxf(mx1, fmaxf(S[nt][2], S[nt][3]));
        }
        mx0 = fmaxf(mx0, __shfl_xor_sync(0xffffffffu, mx0, 1));
        mx0 = fmaxf(mx0, __shfl_xor_sync(0xffffffffu, mx0, 2));
        mx1 = fmaxf(mx1, __shfl_xor_sync(0xffffffffu, mx1, 1));
        mx1 = fmaxf(mx1, __shfl_xor_sync(0xffffffffu, mx1, 2));
        float s0 = 0.f, s1 = 0.f;
#pragma unroll
        for (int nt = 0; nt < 8; ++nt) {
            S[nt][0] = __expf(S[nt][0] - mx0);
            S[nt][1] = __expf(S[nt][1] - mx0);
            S[nt][2] = __expf(S[nt][2] - mx1);
            S[nt][3] = __expf(S[nt][3] - mx1);
            s0 += S[nt][0] + S[nt][1];
            s1 += S[nt][2] + S[nt][3];
        }
        s0 += __shfl_xor_sync(0xffffffffu, s0, 1);
        s0 += __shfl_xor_sync(0xffffffffu, s0, 2);
        s1 += __shfl_xor_sync(0xffffffffu, s1, 1);
        s1 += __shfl_xor_sync(0xffffffffu, s1, 2);
        float i0 = 1.0f / s0, i1 = 1.0f / s1;
#pragma unroll
        for (int nt = 0; nt < 8; ++nt) {
            S[nt][0] *= i0; S[nt][1] *= i0;
            S[nt][2] *= i1; S[nt][3] *= i1;
        }
    }

    u32 Rh[4][4], Rl[4][4];
#pragma unroll
    for (int kt = 0; kt < 4; ++kt) {
        const float* e = S[2 * kt];
        const float* o = S[2 * kt + 1];
        float h;
        Rh[kt][0] = pack2(e[0], e[1]);
        Rh[kt][1] = pack2(e[2], e[3]);
        Rh[kt][2] = pack2(o[0], o[1]);
        Rh[kt][3] = pack2(o[2], o[3]);
        float r0, r1, r2, r3;
        h = __bfloat162float(__float2bfloat16(e[0])); r0 = e[0] - h;
        h = __bfloat162float(__float2bfloat16(e[1])); r1 = e[1] - h;
        h = __bfloat162float(__float2bfloat16(e[2])); r2 = e[2] - h;
        h = __bfloat162float(__float2bfloat16(e[3])); r3 = e[3] - h;
        Rl[kt][0] = pack2(r0, r1);
        Rl[kt][1] = pack2(r2, r3);
        h = __bfloat162float(__float2bfloat16(o[0])); r0 = o[0] - h;
        h = __bfloat162float(__float2bfloat16(o[1])); r1 = o[1] - h;
        h = __bfloat162float(__float2bfloat16(o[2])); r2 = o[2] - h;
        h = __bfloat162float(__float2bfloat16(o[3])); r3 = o[3] - h;
        Rl[kt][2] = pack2(r0, r1);
        Rl[kt][3] = pack2(r2, r3);
    }

    if (is_final) {
        u32 bVh = smem_u32(Vh), bVl = smem_u32(Vl);
        float OB[8][4];
#pragma unroll
        for (int nt = 0; nt < 8; ++nt)
#pragma unroll
            for (int c = 0; c < 4; ++c) OB[nt][c] = 0.f;
#pragma unroll
        for (int kt = 0; kt < 4; ++kt) {
#pragma unroll
            for (int np = 0; np < 4; ++np) {
                u32 boff = (u32)(((kt * 16 + pkrow) * LDB + np * 16 + pncol) * 2);
                u32 b_h[4], b_l[4];
                ldsm4t(bVh + boff, b_h);
                ldsm4t(bVl + boff, b_l);
                mma16816(OB[2 * np], Rh[kt], b_h);
                mma16816(OB[2 * np], Rh[kt], b_l);
                mma16816(OB[2 * np], Rl[kt], b_h);
                mma16816(OB[2 * np + 1], Rh[kt], b_h + 2);
                mma16816(OB[2 * np + 1], Rh[kt], b_l + 2);
                mma16816(OB[2 * np + 1], Rl[kt], b_h + 2);
            }
        }
        long o0 = (long)bh * 262144 + (16 * w + g) * 4096 + s * 64;
        long o1 = o0 + 8 * 4096;
#pragma unroll
        for (int nt = 0; nt < 8; ++nt) {
            int d = nt * 8 + 2 * tq;
            *reinterpret_cast<float2*>(out + o0 + d) =
                make_float2(OB[nt][0], OB[nt][1]);
            *reinterpret_cast<float2*>(out + o1 + d) =
                make_float2(OB[nt][2], OB[nt][3]);
        }
    } else {
        int rA = 16 * w + g, rB = rA + 8;
#pragma unroll
        for (int kt = 0; kt < 4; ++kt) {
            int j0 = (2 * kt) * 8 + 2 * tq;
            int j1 = j0 + 8;
            *reinterpret_cast<u32*>(Lh + rA * LDB + j0) = Rh[kt][0];
            *reinterpret_cast<u32*>(Lh + rA * LDB + j1) = Rh[kt][2];
            *reinterpret_cast<u32*>(Lh + rB * LDB + j0) = Rh[kt][1];
            *reinterpret_cast<u32*>(Lh + rB * LDB + j1) = Rh[kt][3];
            *reinterpret_cast<u32*>(Ll + rA * LDB + j0) = Rl[kt][0];
            *reinterpret_cast<u32*>(Ll + rA * LDB + j1) = Rl[kt][2];
            *reinterpret_cast<u32*>(Ll + rB * LDB + j0) = Rl[kt][1];
            *reinterpret_cast<u32*>(Ll + rB * LDB + j1) = Rl[kt][3];
        }
        __syncthreads();
        if (tid < 64) {
            float wv = 0.f;
#pragma unroll 8
            for (int i = 0; i < 64; ++i)
                wv += __bfloat162float(Lh[i * LDB + tid]) +
                      __bfloat162float(Ll[i * LDB + tid]);
            sW[tid] = 1.0f / wv;
        }
        float QB[8][4];
#pragma unroll
        for (int nt = 0; nt < 8; ++nt)
#pragma unroll
            for (int c = 0; c < 4; ++c) QB[nt][c] = 0.f;
#pragma unroll
        for (int kt = 0; kt < 4; ++kt) {
            int k0 = kt << 4;
            u32 ah[4], al[4];
            u32 aoff = (u32)(((k0 + atrow) * LDB + atcol) * 2);
            ldsm4t(bLh + aoff, ah);
            ldsm4t(bLl + aoff, al);
#pragma unroll
            for (int np = 0; np < 4; ++np) {
                u32 boff = (u32)(((k0 + pkrow) * LDB + np * 16 + pncol) * 2);
                u32 b_h[4], b_l[4];
                ldsm4t(bQh + boff, b_h);
                ldsm4t(bQl + boff, b_l);
                mma16816(QB[2 * np], ah, b_h);
                mma16816(QB[2 * np], ah, b_l);
                mma16816(QB[2 * np], al, b_h);
                mma16816(QB[2 * np + 1], ah, b_h + 2);
                mma16816(QB[2 * np + 1], ah, b_l + 2);
                mma16816(QB[2 * np + 1], al, b_h + 2);
            }
        }
        __syncthreads();
        int j0r = 16 * w + g, j1r = j0r + 8;
        float iw0 = sW[j0r], iw1 = sW[j1r];
        long o0 = (long)bh * 262144 + j0r * 4096 + s * 64;
        long o1 = (long)bh * 262144 + j1r * 4096 + s * 64;
#pragma unroll
        for (int nt = 0; nt < 8; ++nt) {
            int d = nt * 8 + 2 * tq;
            stPair(g_qbarH + o0 + d, g_qbarL + o0 + d,
                   QB[nt][0] * iw0, QB[nt][1] * iw0);
            stPair(g_qbarH + o1 + d, g_qbarL + o1 + d,
                   QB[nt][2] * iw1, QB[nt][3] * iw1);
        }
    }
}

// ---------------------------------------------------------------------------
extern "C" void kernel_launch(void* const* d_in, const int* in_sizes, int n_in,
                              void* d_out, int out_size) {
    const float* Q = (const float*)d_in[0];
    const float* K = (const float*)d_in[1];
    const float* V = (const float*)d_in[2];
    float* out = (float*)d_out;

    cudaFuncSetAttribute(bstep_kernel, cudaFuncAttributeMaxDynamicSharedMemorySize, SMEM_B_BIG);
    cudaFuncSetAttribute(cstep_kernel, cudaFuncAttributeMaxDynamicSharedMemorySize, SMEM_C_BIG);

    // step 0 (uniform L -> qbar == per-s mean of Q)
    qmean_kernel<<<1024, 256>>>(Q);
    bstep_kernel<<<4096, 128, SMEM_B_SMALL>>>(K, V, 1, 0);
    cstep_kernel<<<4096, 128, SMEM_C_SMALL>>>(Q, out, 0);
    // step 1
    bstep_kernel<<<4096, 128, SMEM_B_SMALL>>>(K, V, 0, 0);
    cstep_kernel<<<4096, 128, SMEM_C_SMALL>>>(Q, out, 0);
    // step 2
    bstep_kernel<<<4096, 128, SMEM_B_BIG>>>(K, V, 0, 1);   // + vbar
    cstep_kernel<<<4096, 128, SMEM_C_BIG>>>(Q, out, 1);    // final: out = L vbar
}